// round 17
// baseline (speedup 1.0000x reference)
#include <cuda_runtime.h>
#include <cuda_bf16.h>
#include <cstdint>
#include <cstddef>

#define N_NODES 100000
#define E_EDGES 1000000
#define D_DIM   64
#define NORM_INV 0.01f
#define LN_EPS  1e-5f
#define N_GROUPS 3125            // 100000 / 32 (exact)
#define PACK_BLOCKS 260
#define PREP_BLOCKS 592

// Interleaved per-node table (bf16): [0:64)=u, [64:192) = 16 groups of
// {v[4g..4g+3] , x[4g..4g+3]}  ->  u gather = uint2, v+x gather = ONE uint4.
__device__ __align__(16) __nv_bfloat16 g_uvx[(size_t)N_NODES * 192];
// Packed per-edge metadata {row*256, col*384, dist, emask} (16 B)
__device__ int4 g_ep[(size_t)E_EDGES];

// Exact sigmoid (used output-side in LN)
__device__ __forceinline__ float fsig(float v) {
    return __fdividef(1.0f, 1.0f + __expf(-v));
}
// Fast sigmoid via HW tanh (att path; /100-damped)
__device__ __forceinline__ float fsig_t(float v) {
    float t;
    asm("tanh.approx.f32 %0, %1;" : "=f"(t) : "f"(v * 0.5f));
    return fmaf(t, 0.5f, 0.5f);
}

__device__ __forceinline__ void red_add_v4(float* dst, float a, float b,
                                           float c, float d) {
    asm volatile("red.global.add.v4.f32 [%0], {%1, %2, %3, %4};"
                 :: "l"(dst), "f"(a), "f"(b), "f"(c), "f"(d) : "memory");
}

__device__ __forceinline__ float4 bf16x4_to_f4(uint2 r) {
    const float2 a = __bfloat1622float2(*reinterpret_cast<__nv_bfloat162*>(&r.x));
    const float2 b = __bfloat1622float2(*reinterpret_cast<__nv_bfloat162*>(&r.y));
    return make_float4(a.x, a.y, b.x, b.y);
}

__device__ __forceinline__ unsigned pack_bf2(float a, float b) {
    const __nv_bfloat162 t = __float22bfloat162_rn(make_float2(a, b));
    return *reinterpret_cast<const unsigned*>(&t);
}

// ---------------------------------------------------------------------------
// Kernel 1 (fused): blocks [0, PACK_BLOCKS) pack g_ep and exit; remaining
// blocks run the prep_uv pipeline on 32-node groups (exactly 3125 groups):
//   A: stage h (f32) into sUVX rows; x = Wlin@h + blin (fp32) -> d_out;
//      bf16(x) into the x-slots of the SAME sUVX rows;
//   B: u||v = [A;B] @ x via mma.sync (2 warps split each tile-half);
//   C: coalesced uint4 flush sUVX -> g_uvx.
// GROUP=32 -> smem 48.9 KB -> 4 blocks/SM (occ 50%).
// ---------------------------------------------------------------------------
#define PREPUV_SMEM ((64*68 + 64) * 4 + 128*72*2 + 32*200*2)   // 48,896 B

__global__ void __launch_bounds__(256, 4)
prep_uv_kernel(const float* __restrict__ h,
               const float* __restrict__ Wlin,
               const float* __restrict__ blin,
               const float* __restrict__ W1,
               const int* __restrict__ edges,
               const float* __restrict__ dist,
               const float* __restrict__ emask,
               float* __restrict__ out_res)
{
    const int tid = threadIdx.x;

    // ---------------- Pack specialization (blocks 0..PACK_BLOCKS-1) ------
    if (blockIdx.x < PACK_BLOCKS) {
        const int stride = PACK_BLOCKS * 256;
        for (int e = blockIdx.x * 256 + tid; e < E_EDGES; e += stride) {
            int4 m;
            m.x = __ldg(edges + e) << 8;                 // row * 256
            m.y = __ldg(edges + E_EDGES + e) * 384;      // col * 384
            m.z = __float_as_int(__ldg(dist + e));
            m.w = __float_as_int(__ldg(emask + e));
            g_ep[e] = m;
        }
        return;
    }
    const int bid = blockIdx.x - PACK_BLOCKS;            // 0..PREP_BLOCKS-1

    extern __shared__ float smem[];
    float*          sWs  = smem;                        // 64*68 f32
    float*          sbs  = sWs + 64 * 68;               // 64 f32
    __nv_bfloat16*  sW1  = (__nv_bfloat16*)(sbs + 64);  // 128*72 bf16
    char*           sUVX = (char*)(sW1 + 128 * 72);     // 32 rows x 400 B

    for (int i = tid; i < 64 * 64; i += 256)
        sWs[(i >> 6) * 68 + (i & 63)] = Wlin[i];
    if (tid < 64) sbs[tid] = blin[tid];
    for (int i = tid; i < 128 * 64; i += 256) {
        const int j = i >> 6, k = i & 63;
        const float wv = (j < 64) ? __ldg(W1 + j * 129 + k)
                                  : __ldg(W1 + (j - 64) * 129 + 64 + k);
        sW1[j * 72 + k] = __float2bfloat16(wv);
    }
    __syncthreads();

    const int lane = tid & 31;
    const int w    = tid >> 5;
    const int g    = lane >> 2;     // MMA group id (0..7)
    const int t    = lane & 3;      // thread-in-group

    const float4* w0p = ((const float4*)sWs) + lane * 17;
    const float4* w1p = ((const float4*)sWs) + (lane + 32) * 17;
    const float bj0 = sbs[lane], bj1 = sbs[lane + 32];
    const float4* hf4 = (const float4*)h;

    // interleaved x-slot (bytes) for dim d=lane: (64+(d>>2)*8+4+(d&3))*2
    const unsigned xslotB = (64u + ((lane >> 2) << 3) + 4u + (lane & 3)) * 2u;

    const int tl   = w >> 2;        // phase-B tile within group (0..1)
    const int half = (w >> 1) & 1;  // 0 -> u, 1 -> v
    const int nth  = w & 1;         // nt-range half (0..1)

    for (int grp = bid; grp < N_GROUPS; grp += PREP_BLOCKS) {
        const int nb = grp * 32 + w * 4;

        // ------------- Phase A: h staging + x GEMM (4 nodes/warp) --------
        {
            char* rows = sUVX + (size_t)(w * 4) * 400;   // this warp's rows
            #pragma unroll
            for (int ep = 0; ep < 4; ep += 2) {
                const int e  = ep + (lane >> 4);
                const int li = lane & 15;
                *(float4*)(rows + e * 400 + li * 16) =
                    hf4[(size_t)(nb + e) * 16 + li];
            }
            __syncwarp();

            float acc0[4], acc1[4];
            #pragma unroll
            for (int e = 0; e < 4; e++) { acc0[e] = bj0; acc1[e] = bj1; }

            #pragma unroll 4
            for (int kk = 0; kk < 16; kk++) {
                const float4 a = w0p[kk], b = w1p[kk];
                #pragma unroll
                for (int e = 0; e < 4; e++) {
                    const float4 xv = *(const float4*)(rows + e * 400 + kk * 16);
                    acc0[e] = fmaf(a.x, xv.x, acc0[e]);
                    acc0[e] = fmaf(a.y, xv.y, acc0[e]);
                    acc0[e] = fmaf(a.z, xv.z, acc0[e]);
                    acc0[e] = fmaf(a.w, xv.w, acc0[e]);
                    acc1[e] = fmaf(b.x, xv.x, acc1[e]);
                    acc1[e] = fmaf(b.y, xv.y, acc1[e]);
                    acc1[e] = fmaf(b.z, xv.z, acc1[e]);
                    acc1[e] = fmaf(b.w, xv.w, acc1[e]);
                }
            }
            __syncwarp();   // all h reads done -> rows may be overwritten

            #pragma unroll
            for (int e = 0; e < 4; e++) {
                const size_t n64 = (size_t)(nb + e) * 64;
                out_res[n64 + lane]      = acc0[e];
                out_res[n64 + lane + 32] = acc1[e];
                char* row = rows + e * 400;
                *(__nv_bfloat16*)(row + xslotB)        = __float2bfloat16(acc0[e]);
                *(__nv_bfloat16*)(row + xslotB + 128u) = __float2bfloat16(acc1[e]);
            }
        }
        __syncthreads();

        // ------------- Phase B: u/v MMA from sUVX x-slots ----------------
        // 2 warps per (tile, half): nth selects nt range [nth*4, nth*4+4).
        {
            const int tile_g = grp * 2 + tl;
            const char* xr0 = sUVX + (size_t)(tl * 16 + g) * 400;
            const char* xr1 = xr0 + 8 * 400;

            unsigned a[4][4];
            #pragma unroll
            for (int kk = 0; kk < 4; kk++) {
                const int d0 = kk * 16 + 2 * t;
                const int d1 = d0 + 8;
                const unsigned o0 = (64u + ((d0 >> 2) << 3) + 4u + (d0 & 3)) * 2u;
                const unsigned o1 = (64u + ((d1 >> 2) << 3) + 4u + (d1 & 3)) * 2u;
                a[kk][0] = *(const unsigned*)(xr0 + o0);
                a[kk][1] = *(const unsigned*)(xr1 + o0);
                a[kk][2] = *(const unsigned*)(xr0 + o1);
                a[kk][3] = *(const unsigned*)(xr1 + o1);
            }
            (void)tile_g;

            char* or0 = sUVX + (size_t)(tl * 16 + g) * 400;
            char* or1 = or0 + 8 * 400;

            #pragma unroll
            for (int nt = nth * 4; nt < nth * 4 + 4; nt++) {
                float acc[4] = {0.f, 0.f, 0.f, 0.f};
                const __nv_bfloat16* wrow = sW1 + (half * 64 + nt * 8 + g) * 72;
                #pragma unroll
                for (int kk = 0; kk < 4; kk++) {
                    const unsigned b0 = *(const unsigned*)(wrow + kk * 16 + 2 * t);
                    const unsigned b1 = *(const unsigned*)(wrow + kk * 16 + 2 * t + 8);
                    asm volatile(
                        "mma.sync.aligned.m16n8k16.row.col.f32.bf16.bf16.f32 "
                        "{%0,%1,%2,%3}, {%4,%5,%6,%7}, {%8,%9}, {%0,%1,%2,%3};"
                        : "+f"(acc[0]), "+f"(acc[1]), "+f"(acc[2]), "+f"(acc[3])
                        : "r"(a[kk][0]), "r"(a[kk][1]), "r"(a[kk][2]), "r"(a[kk][3]),
                          "r"(b0), "r"(b1));
                }
                const int c = nt * 8 + 2 * t;         // col within half (even)
                const unsigned slotB = ((half == 0)
                    ? (unsigned)c
                    : 64u + (unsigned)((c >> 2) << 3) + (unsigned)(c & 3)) * 2u;
                *(unsigned*)(or0 + slotB) = pack_bf2(acc[0], acc[1]);
                *(unsigned*)(or1 + slotB) = pack_bf2(acc[2], acc[3]);
            }
        }
        __syncthreads();

        // ------------- Phase C: coalesced flush sUVX -> g_uvx ------------
        {
            const int base = grp * 32;
            #pragma unroll
            for (int i = tid; i < 768; i += 256) {      // 32 nodes x 24 uint4
                const int node  = i / 24;
                const int chunk = i % 24;
                const uint4 val = *(const uint4*)(sUVX + node * 400 + chunk * 16);
                *(uint4*)((char*)g_uvx + (size_t)(base + node) * 384 + chunk * 16) = val;
            }
        }
        __syncthreads();
    }
}

// ---------------------------------------------------------------------------
// Kernel 2 (edge): t = u[row]+v[col]+wd*d+b1; att = sig(W2.silu(t)+b2);
// fp32 red.global.add.v4 of att*x_col into d_out[row].
// ---------------------------------------------------------------------------
__global__ void __launch_bounds__(256, 6)
edge_kernel(const float* __restrict__ W1,   // [64][129]
            const float* __restrict__ b1,
            const float* __restrict__ W2,   // [64]
            const float* __restrict__ b2p,
            float* __restrict__ agg)        // d_out
{
    const int lane = threadIdx.x & 31;
    const int w    = threadIdx.x >> 5;
    const int hw   = lane >> 4;      // which edge of the pair
    const int li   = lane & 15;      // dim group within edge

    const float4 w2_4 = ((const float4*)W2)[li];
    const float4 b1_4 = ((const float4*)b1)[li];
    float4 wd_4;
    wd_4.x = __ldg(W1 + (size_t)(li * 4 + 0) * 129 + 128);
    wd_4.y = __ldg(W1 + (size_t)(li * 4 + 1) * 129 + 128);
    wd_4.z = __ldg(W1 + (size_t)(li * 4 + 2) * 129 + 128);
    wd_4.w = __ldg(W1 + (size_t)(li * 4 + 3) * 129 + 128);
    const float b2 = b2p[0];

    const char* uvx  = (const char*)g_uvx;   // 384 B per node
    char*       aggc = (char*)agg;           // 256 B per node

    const int warpGlobal = blockIdx.x * 8 + w;
    const int nWarps     = gridDim.x * 8;

    for (int eb = warpGlobal * 4; eb < E_EDGES; eb += nWarps * 4) {
        int4 m[2];
        m[0] = __ldg(g_ep + eb + hw);
        m[1] = __ldg(g_ep + eb + 2 + hw);

        uint2 ur[2];
        uint4 vx[2];
        #pragma unroll
        for (int s = 0; s < 2; s++) {
            const int uoff = m[s].x + (m[s].x >> 1);       // row*384
            ur[s] = __ldg((const uint2*)(uvx + uoff + li * 8));
            vx[s] = __ldg((const uint4*)(uvx + m[s].y + 128 + li * 16));
        }

        #pragma unroll
        for (int s = 0; s < 2; s++) {
            const float d  = __int_as_float(m[s].z);
            const float em = __int_as_float(m[s].w);
            const float4 u4 = bf16x4_to_f4(ur[s]);
            const float4 v4 = bf16x4_to_f4(make_uint2(vx[s].x, vx[s].y));
            const float4 x4 = bf16x4_to_f4(make_uint2(vx[s].z, vx[s].w));

            float4 t;
            t.x = fmaf(d, wd_4.x, u4.x + v4.x + b1_4.x);
            t.y = fmaf(d, wd_4.y, u4.y + v4.y + b1_4.y);
            t.z = fmaf(d, wd_4.z, u4.z + v4.z + b1_4.z);
            t.w = fmaf(d, wd_4.w, u4.w + v4.w + b1_4.w);

            const float h0 = t.x * fsig_t(t.x);
            const float h1 = t.y * fsig_t(t.y);
            const float h2 = t.z * fsig_t(t.z);
            const float h3 = t.w * fsig_t(t.w);

            float p = fmaf(h0, w2_4.x,
                      fmaf(h1, w2_4.y,
                      fmaf(h2, w2_4.z, h3 * w2_4.w)));
            #pragma unroll
            for (int off = 8; off; off >>= 1)          // reduce within 16 lanes
                p += __shfl_xor_sync(0xffffffffu, p, off);

            const float att = fsig_t(p + b2) * em * NORM_INV;

            float* dst = (float*)(aggc + m[s].x + li * 16);
            red_add_v4(dst, x4.x * att, x4.y * att, x4.z * att, x4.w * att);
        }
    }
}

// ---------------------------------------------------------------------------
// Kernel 3: out = silu(LN(io)).  io holds x + agg (fp32).
// 8 lanes per row, 8 floats (2 x float4) per thread, 4 rows per warp.
// ---------------------------------------------------------------------------
__global__ void ln_kernel(const float* __restrict__ g,
                          const float* __restrict__ bln,
                          float* __restrict__ io)
{
    const int lane = threadIdx.x & 31;
    const int w    = threadIdx.x >> 5;
    const int li   = lane & 7;                    // 8 lanes per row
    const int row  = blockIdx.x * 32 + w * 4 + (lane >> 3);
    if (row >= N_NODES) return;

    float4 va = ((const float4*)io)[(size_t)row * 16 + li * 2];
    float4 vb = ((const float4*)io)[(size_t)row * 16 + li * 2 + 1];

    float s  = (va.x + va.y + va.z + va.w) + (vb.x + vb.y + vb.z + vb.w);
    float sq = fmaf(va.x, va.x, fmaf(va.y, va.y, fmaf(va.z, va.z, va.w * va.w)));
    sq = fmaf(vb.x, vb.x, fmaf(vb.y, vb.y, fmaf(vb.z, vb.z, fmaf(vb.w, vb.w, sq))));
    #pragma unroll
    for (int off = 4; off; off >>= 1) {
        s  += __shfl_xor_sync(0xffffffffu, s,  off);
        sq += __shfl_xor_sync(0xffffffffu, sq, off);
    }
    const float mu  = s * (1.0f / 64.0f);
    const float var = fmaf(-mu, mu, sq * (1.0f / 64.0f));
    const float rs  = rsqrtf(var + LN_EPS);

    const float4 ga = __ldg((const float4*)g + li * 2);
    const float4 gb = __ldg((const float4*)g + li * 2 + 1);
    const float4 ba = __ldg((const float4*)bln + li * 2);
    const float4 bb = __ldg((const float4*)bln + li * 2 + 1);

    float4 oa, ob;
    oa.x = fmaf((va.x - mu) * rs, ga.x, ba.x);
    oa.y = fmaf((va.y - mu) * rs, ga.y, ba.y);
    oa.z = fmaf((va.z - mu) * rs, ga.z, ba.z);
    oa.w = fmaf((va.w - mu) * rs, ga.w, ba.w);
    ob.x = fmaf((vb.x - mu) * rs, gb.x, bb.x);
    ob.y = fmaf((vb.y - mu) * rs, gb.y, bb.y);
    ob.z = fmaf((vb.z - mu) * rs, gb.z, bb.z);
    ob.w = fmaf((vb.w - mu) * rs, gb.w, bb.w);
    oa.x *= fsig(oa.x);  oa.y *= fsig(oa.y);
    oa.z *= fsig(oa.z);  oa.w *= fsig(oa.w);
    ob.x *= fsig(ob.x);  ob.y *= fsig(ob.y);
    ob.z *= fsig(ob.z);  ob.w *= fsig(ob.w);

    ((float4*)io)[(size_t)row * 16 + li * 2]     = oa;
    ((float4*)io)[(size_t)row * 16 + li * 2 + 1] = ob;
}

// ---------------------------------------------------------------------------
// Launch: prep_uv(pack ∥ prep, fused) -> edge -> LN.
// ---------------------------------------------------------------------------
extern "C" void kernel_launch(void* const* d_in, const int* in_sizes, int n_in,
                              void* d_out, int out_size)
{
    const float* h     = (const float*)d_in[0];
    const float* dist  = (const float*)d_in[1];
    const int*   edges = (const int*)d_in[2];   // JAX x64-disabled => int32
    /* d_in[3] node_mask: unused by the reference */
    const float* emask = (const float*)d_in[4];
    const float* Wlin  = (const float*)d_in[5];
    const float* blin  = (const float*)d_in[6];
    const float* W1    = (const float*)d_in[7];
    const float* b1    = (const float*)d_in[8];
    const float* W2    = (const float*)d_in[9];
    const float* b2    = (const float*)d_in[10];
    const float* lng   = (const float*)d_in[11];
    const float* lnb   = (const float*)d_in[12];
    float* out = (float*)d_out;

    cudaFuncSetAttribute(prep_uv_kernel,
                         cudaFuncAttributeMaxDynamicSharedMemorySize, PREPUV_SMEM);

    prep_uv_kernel<<<PACK_BLOCKS + PREP_BLOCKS, 256, PREPUV_SMEM>>>(
        h, Wlin, blin, W1, edges, dist, emask, out);
    edge_kernel<<<888, 256>>>(W1, b1, W2, b2, out);      // 6 blocks/SM, 1 wave
    ln_kernel<<<(N_NODES + 31) / 32, 256>>>(lng, lnb, out);
}